// round 14
// baseline (speedup 1.0000x reference)
#include <cuda_runtime.h>
#include <cuda_bf16.h>
#include <cstdint>

#define BATCH 4
#define CDIM 128
#define CCTX 256
#define NPIX 4096
#define HS 32
#define NS 1024
#define HH 64
#define WW 64

// ---------------- scratch (device globals; no allocation) ----------------
__device__ __nv_bfloat16 g_qh[(size_t)BATCH*NPIX*CDIM];   // Q bf16 [b][n][c]
__device__ __nv_bfloat16 g_kh[(size_t)BATCH*NPIX*CDIM];   // K bf16 [b][m][c]
__device__ __nv_bfloat16 g_vh[(size_t)BATCH*CDIM*NPIX];   // V bf16 [b][c][m]
__device__ float g_kt[(size_t)BATCH*NS*CDIM];             // K conv out fp32 [b][ms][c]
__device__ float g_vs[(size_t)BATCH*CDIM*NS];             // V conv out fp32 [b][c][ms]
__device__ __nv_bfloat16 g_P[(size_t)BATCH*NPIX*NPIX];    // exp(S) bf16 [b][n][m]
__device__ float g_psum[(size_t)BATCH*32*NPIX];           // row partial sums [b][mtile][n]
__device__ float g_rinv[(size_t)BATCH*NPIX];              // 1/rowsum [b][n]
__device__ float g_att[(size_t)BATCH*CDIM*NPIX];          // attn out fp32 [b][c][n]
__device__ float g_Wt [9*CDIM*CDIM];                      // [tap][ci][co]

// ---------------- helpers ----------------
__device__ __forceinline__ uint32_t smem_u32(const void* p){
  uint32_t a;
  asm("{ .reg .u64 t; cvta.to.shared.u64 t, %1; cvt.u32.u64 %0, t; }" : "=r"(a) : "l"(p));
  return a;
}
__device__ __forceinline__ void cpasync16(void* sdst, const void* gsrc){
  uint32_t d = smem_u32(sdst);
  asm volatile("cp.async.cg.shared.global [%0], [%1], 16;" :: "r"(d), "l"(gsrc) : "memory");
}
#define CP_COMMIT() asm volatile("cp.async.commit_group;" ::: "memory")
#define CP_WAIT0()  asm volatile("cp.async.wait_group 0;" ::: "memory")
#define CP_WAIT1()  asm volatile("cp.async.wait_group 1;" ::: "memory")

// HMMA m16n8k16 bf16 -> fp32
__device__ __forceinline__ void mma16816(float* d, const uint32_t* a, const uint32_t* b){
  asm volatile("mma.sync.aligned.m16n8k16.row.col.f32.bf16.bf16.f32 "
    "{%0,%1,%2,%3}, {%4,%5,%6,%7}, {%8,%9}, {%0,%1,%2,%3};"
    : "+f"(d[0]), "+f"(d[1]), "+f"(d[2]), "+f"(d[3])
    : "r"(a[0]), "r"(a[1]), "r"(a[2]), "r"(a[3]), "r"(b[0]), "r"(b[1]));
}

// swizzled LDS of a bf16 pair: row-major rows of RW bf16 elems, word = pair index
template<int RW>
__device__ __forceinline__ uint32_t ldsw(const __nv_bfloat16* base, int r, int w){
  return *(const uint32_t*)(base + r*RW + 2*(w ^ ((r&7)<<2)));
}

// ---------------- packed fp32 helpers (FFMA2) for fp32 kernels ----------------
__device__ __forceinline__ unsigned long long pack2(float x){
  unsigned int xi = __float_as_uint(x);
  unsigned long long r;
  asm("mov.b64 %0, {%1, %1};" : "=l"(r) : "r"(xi));
  return r;
}
__device__ __forceinline__ unsigned long long ffma2u(unsigned long long a,
                                                     unsigned long long b,
                                                     unsigned long long c){
  asm("fma.rn.f32x2 %0, %1, %2, %0;" : "+l"(c) : "l"(a), "l"(b));
  return c;
}
__device__ __forceinline__ float lo2(unsigned long long v){ return __uint_as_float((unsigned int)v); }
__device__ __forceinline__ float hi2(unsigned long long v){ return __uint_as_float((unsigned int)(v>>32)); }

// ---------------- 1x1 conv GEMM ----------------
// DST: 0 -> Q bf16 [b][n][c]; 1 -> g_vs fp32 [b][c][ms]; 2 -> g_kt fp32 [b][ms][c]
template<int CI, int DST>
__global__ __launch_bounds__(256) void conv1x1_kernel(
    const float* __restrict__ in, const float* __restrict__ W,
    const float* __restrict__ bias, int Npix)
{
  __shared__ float Ash[16][64];
  __shared__ float Bsh[16][68];
  const int n0 = blockIdx.x*64, co0 = blockIdx.y*64, b = blockIdx.z;
  const int tid = threadIdx.x, tx = tid & 15, ty = tid >> 4;
  const float* inb = in + (size_t)b*CI*Npix;
  float acc[4][4];
  #pragma unroll
  for (int i=0;i<4;i++)
    #pragma unroll
    for (int j=0;j<4;j++) acc[i][j]=0.f;

  for (int k0=0;k0<CI;k0+=16){
    __syncthreads();
    #pragma unroll
    for (int r=0;r<4;r++){
      int idx = tid + r*256;
      Ash[idx>>6][idx&63] = inb[(size_t)(k0+(idx>>6))*Npix + n0 + (idx&63)];
    }
    #pragma unroll
    for (int r=0;r<4;r++){
      int idx = tid + r*256;
      int cc = idx>>4, kk = idx&15;
      Bsh[kk][cc] = W[(size_t)(co0+cc)*CI + k0+kk];
    }
    __syncthreads();
    #pragma unroll
    for (int kk=0;kk<16;kk++){
      float a[4], bb[4];
      #pragma unroll
      for (int u=0;u<4;u++) a[u]=Ash[kk][tx*4+u];
      #pragma unroll
      for (int u=0;u<4;u++) bb[u]=Bsh[kk][ty*4+u];
      #pragma unroll
      for (int i=0;i<4;i++)
        #pragma unroll
        for (int j=0;j<4;j++) acc[i][j] += bb[i]*a[j];
    }
  }
  #pragma unroll
  for (int i=0;i<4;i++){
    int co = co0+ty*4+i;
    float bi = bias[co];
    #pragma unroll
    for (int j=0;j<4;j++){
      int n = n0+tx*4+j;
      float v = acc[i][j]+bi;
      if (DST==0)      g_qh[((size_t)b*NPIX + n)*CDIM + co] = __float2bfloat16(v);
      else if (DST==1) g_vs[((size_t)b*CDIM + co)*NS + n] = v;
      else             g_kt[((size_t)b*NS + n)*CDIM + co] = v;
    }
  }
}

// ---------------- bilinear 2x upsample helpers ----------------
__device__ __forceinline__ void bsrc(int o, int &i0, int &i1, float &w1){
  float s = 0.5f*(float)o - 0.25f;
  float f = floorf(s);
  w1 = s - f;
  int i = (int)f;
  i0 = i < 0 ? 0 : i;
  i1 = (i+1 > HS-1) ? (HS-1) : (i+1);
}

// V: [c][ms] fp32 -> [c][m] bf16
__global__ void upsample_plane_kernel(){
  __shared__ float sch[HS*HS];
  int c = blockIdx.x, b = blockIdx.y;
  const float* src = g_vs + ((size_t)b*CDIM + c)*NS;
  for (int i=threadIdx.x;i<NS;i+=256) sch[i]=src[i];
  __syncthreads();
  __nv_bfloat16* dst = g_vh + ((size_t)b*CDIM + c)*NPIX;
  for (int p=threadIdx.x;p<NPIX;p+=256){
    int h=p>>6, w=p&63;
    int y0,y1,x0,x1; float wy,wx;
    bsrc(h,y0,y1,wy); bsrc(w,x0,x1,wx);
    float v = (1.f-wy)*((1.f-wx)*sch[y0*HS+x0]+wx*sch[y0*HS+x1])
            +      wy *((1.f-wx)*sch[y1*HS+x0]+wx*sch[y1*HS+x1]);
    dst[p] = __float2bfloat16(v);
  }
}

// K: [ms][c] fp32 -> [m][c] bf16
__global__ void upsample_last_kernel(){
  int h = blockIdx.x, b = blockIdx.y;
  int c  = threadIdx.x & 127;
  int wo = threadIdx.x >> 7;
  int y0,y1; float wy; bsrc(h,y0,y1,wy);
  const float* src = g_kt + (size_t)b*NS*CDIM;
  __nv_bfloat16* dst = g_kh + ((size_t)b*NPIX + (size_t)h*WW)*CDIM;
  for (int w=wo; w<WW; w+=2){
    int x0,x1; float wx; bsrc(w,x0,x1,wx);
    float v00=src[(size_t)(y0*HS+x0)*CDIM+c], v01=src[(size_t)(y0*HS+x1)*CDIM+c];
    float v10=src[(size_t)(y1*HS+x0)*CDIM+c], v11=src[(size_t)(y1*HS+x1)*CDIM+c];
    float v = (1.f-wy)*((1.f-wx)*v00+wx*v01) + wy*((1.f-wx)*v10+wx*v11);
    dst[(size_t)w*CDIM+c] = __float2bfloat16(v);
  }
}

// ---------------- MMA1: S[n][m] = Q.K^T, fused P = exp(S) bf16 + row partial sums ------
// block 256 = 8 warps, warp tile 32(n) x 64(m). smem: Qs 32KB | Ks 32KB | psum 512B
__global__ __launch_bounds__(256) void mma1_kernel(){
  extern __shared__ char smem[];
  __nv_bfloat16* Qs = (__nv_bfloat16*)smem;
  __nv_bfloat16* Ks = (__nv_bfloat16*)(smem + 32768);
  float* psumS = (float*)(smem + 65536);

  const int tid = threadIdx.x, lane = tid&31, wid = tid>>5;
  const int tig = lane&3, g = lane>>2;
  const int wr = wid&3, wc = wid>>2;                 // n quadrant / m half
  const int m0 = blockIdx.x*128, n0 = blockIdx.y*128, b = blockIdx.z;

  const uint4* gq = (const uint4*)(g_qh + ((size_t)b*NPIX + n0)*CDIM);
  const uint4* gk = (const uint4*)(g_kh + ((size_t)b*NPIX + m0)*CDIM);
  #pragma unroll
  for (int r=0;r<8;r++){
    int i = tid + r*256;
    int row = i>>4, seg = i&15;
    int so = row*128 + ((seg ^ (row&7))<<3);
    cpasync16(Qs + so, gq + i);
    cpasync16(Ks + so, gk + i);
  }
  CP_COMMIT();
  if (tid < 128) psumS[tid] = 0.f;
  CP_WAIT0();
  __syncthreads();

  float acc[2][8][4];
  #pragma unroll
  for (int ti=0;ti<2;ti++)
    #pragma unroll
    for (int tj=0;tj<8;tj++)
      #pragma unroll
      for (int u=0;u<4;u++) acc[ti][tj][u]=0.f;

  #pragma unroll
  for (int ks=0;ks<8;ks++){
    const int w0 = ks*8 + tig;
    uint32_t aF[2][4], bF[8][2];
    #pragma unroll
    for (int ti=0;ti<2;ti++){
      int r = wr*32 + ti*16 + g;
      aF[ti][0] = ldsw<128>(Qs, r,   w0);
      aF[ti][1] = ldsw<128>(Qs, r+8, w0);
      aF[ti][2] = ldsw<128>(Qs, r,   w0+4);
      aF[ti][3] = ldsw<128>(Qs, r+8, w0+4);
    }
    #pragma unroll
    for (int tj=0;tj<8;tj++){
      int r = wc*64 + tj*8 + g;
      bF[tj][0] = ldsw<128>(Ks, r, w0);
      bF[tj][1] = ldsw<128>(Ks, r, w0+4);
    }
    #pragma unroll
    for (int ti=0;ti<2;ti++)
      #pragma unroll
      for (int tj=0;tj<8;tj++)
        mma16816(acc[ti][tj], aF[ti], bF[tj]);
  }

  // epilogue: exp -> P bf16, rowsum partials
  __nv_bfloat16* Pb = g_P + (size_t)b*NPIX*NPIX;
  float ps[2][2] = {{0.f,0.f},{0.f,0.f}};
  #pragma unroll
  for (int ti=0;ti<2;ti++){
    int r0 = n0 + wr*32 + ti*16 + g;
    #pragma unroll
    for (int tj=0;tj<8;tj++){
      int col = m0 + wc*64 + tj*8 + tig*2;
      float e0=__expf(acc[ti][tj][0]), e1=__expf(acc[ti][tj][1]);
      float e2=__expf(acc[ti][tj][2]), e3=__expf(acc[ti][tj][3]);
      ps[ti][0]+=e0+e1; ps[ti][1]+=e2+e3;
      __nv_bfloat162 p01=__floats2bfloat162_rn(e0,e1), p23=__floats2bfloat162_rn(e2,e3);
      *(uint32_t*)(Pb + (size_t)r0*NPIX + col)     = *(uint32_t*)&p01;
      *(uint32_t*)(Pb + (size_t)(r0+8)*NPIX + col) = *(uint32_t*)&p23;
    }
  }
  #pragma unroll
  for (int ti=0;ti<2;ti++)
    #pragma unroll
    for (int hf=0;hf<2;hf++){
      float v = ps[ti][hf];
      v += __shfl_xor_sync(0xffffffffu, v, 1);
      v += __shfl_xor_sync(0xffffffffu, v, 2);
      if (tig==0) atomicAdd(&psumS[wr*32 + ti*16 + hf*8 + g], v);
    }
  __syncthreads();
  if (tid < 128)
    g_psum[((size_t)b*32 + blockIdx.x)*NPIX + n0 + tid] = psumS[tid];
}

// ---------------- rinv: 1/rowsum ----------------
__global__ void rinv_kernel(){
  int idx = blockIdx.x*256 + threadIdx.x;   // 16384
  int b = idx >> 12, n = idx & 4095;
  float s = 0.f;
  #pragma unroll
  for (int mt=0; mt<32; mt++) s += g_psum[((size_t)b*32 + mt)*NPIX + n];
  g_rinv[idx] = 1.f/s;
}

// ---------------- MMA2: att[c][n] = (V . P^T) * rinv[n], K=4096, 2-stage cp.async ------
// block 256 = 8 warps, warp tile 32(c) x 64(n). smem: V 2x16KB | P 2x16KB | rinv 512B
__global__ __launch_bounds__(256) void mma2_kernel(){
  extern __shared__ char smem[];
  const int tid = threadIdx.x, lane = tid&31, wid = tid>>5;
  const int tig = lane&3, g = lane>>2;
  const int wcq = wid&3, wcn = wid>>2;               // c quadrant / n half
  const int n0 = blockIdx.x*128, b = blockIdx.y;
  float* rinvS = (float*)(smem + 65536);

  const uint4* gv = (const uint4*)(g_vh + (size_t)b*CDIM*NPIX);
  const uint4* gp = (const uint4*)(g_P  + ((size_t)b*NPIX + n0)*NPIX);
  if (tid < 128) rinvS[tid] = g_rinv[(size_t)b*NPIX + n0 + tid];

  auto stage = [&](int ch, int buf){
    __nv_bfloat16* Vb = (__nv_bfloat16*)(smem + buf*16384);
    __nv_bfloat16* Pt = (__nv_bfloat16*)(smem + 32768 + buf*16384);
    #pragma unroll
    for (int r=0;r<4;r++){
      int i = tid + r*256;
      int row = i>>3, seg = i&7;
      cpasync16(Vb + row*64 + ((seg ^ (row&7))<<3), gv + (size_t)row*512 + ch*8 + seg);
    }
    #pragma unroll
    for (int r=0;r<4;r++){
      int i = tid + r*256;
      int row = i>>3, seg = i&7;
      cpasync16(Pt + row*64 + ((seg ^ (row&7))<<3), gp + (size_t)row*512 + ch*8 + seg);
    }
    CP_COMMIT();
  };

  float acc[2][8][4];
  #pragma unroll
  for (int ti=0;ti<2;ti++)
    #pragma unroll
    for (int tj=0;tj<8;tj++)
      #pragma unroll
      for (int u=0;u<4;u++) acc[ti][tj][u]=0.f;

  stage(0,0);
  stage(1,1);
  int buf = 0;
  for (int ch=0; ch<64; ch++){
    CP_WAIT1();
    __syncthreads();
    const __nv_bfloat16* Vb = (const __nv_bfloat16*)(smem + buf*16384);
    const __nv_bfloat16* Pt = (const __nv_bfloat16*)(smem + 32768 + buf*16384);
    #pragma unroll
    for (int ks=0;ks<4;ks++){
      const int w0 = ks*8 + tig;
      uint32_t aF[2][4], bF[8][2];
      #pragma unroll
      for (int ti=0;ti<2;ti++){
        int r = wcq*32 + ti*16 + g;
        aF[ti][0] = ldsw<64>(Vb, r,   w0);
        aF[ti][1] = ldsw<64>(Vb, r+8, w0);
        aF[ti][2] = ldsw<64>(Vb, r,   w0+4);
        aF[ti][3] = ldsw<64>(Vb, r+8, w0+4);
      }
      #pragma unroll
      for (int tj=0;tj<8;tj++){
        int r = wcn*64 + tj*8 + g;
        bF[tj][0] = ldsw<64>(Pt, r, w0);
        bF[tj][1] = ldsw<64>(Pt, r, w0+4);
      }
      #pragma unroll
      for (int ti=0;ti<2;ti++)
        #pragma unroll
        for (int tj=0;tj<8;tj++)
          mma16816(acc[ti][tj], aF[ti], bF[tj]);
    }
    __syncthreads();
    if (ch+2 < 64) stage(ch+2, buf);
    buf ^= 1;
  }

  // epilogue: scale by rinv, store fp32
  #pragma unroll
  for (int ti=0;ti<2;ti++){
    int crow = wcq*32 + ti*16 + g;
    #pragma unroll
    for (int tj=0;tj<8;tj++){
      int col = wcn*64 + tj*8 + tig*2;
      float ri0 = rinvS[col], ri1 = rinvS[col+1];
      float2 v0 = make_float2(acc[ti][tj][0]*ri0, acc[ti][tj][1]*ri1);
      float2 v1 = make_float2(acc[ti][tj][2]*ri0, acc[ti][tj][3]*ri1);
      *(float2*)(g_att + ((size_t)b*CDIM + crow)*NPIX + n0 + col)   = v0;
      *(float2*)(g_att + ((size_t)b*CDIM + crow+8)*NPIX + n0 + col) = v1;
    }
  }
}

// ---------------- Wp transpose to [tap][ci][co] ----------------
__global__ void wt_kernel(const float* __restrict__ Wp){
  int i = blockIdx.x*256+threadIdx.x;
  if (i < 9*CDIM*CDIM){
    int tap = i/(CDIM*CDIM), r = i%(CDIM*CDIM);
    int ci = r>>7, co = r&127;
    g_Wt[i] = Wp[((size_t)co*CDIM + ci)*9 + tap];
  }
}

// ---------------- final: out = sr + gamma*(bp + conv3x3(att)) ----------------
__global__ __launch_bounds__(256) void conv3_kernel(
  const float* __restrict__ sr, const float* __restrict__ bp,
  const float* __restrict__ gamma, float* __restrict__ out)
{
  __shared__ float Ash[8][64];
  __shared__ float Bsh[8][128];
  const int h = blockIdx.x, b = blockIdx.y;
  const int tid=threadIdx.x, tx=tid&15, ty=tid>>4;
  const float* att = g_att + (size_t)b*CDIM*NPIX;
  unsigned long long acc[8][2];
  #pragma unroll
  for (int i=0;i<8;i++){ acc[i][0]=0ull; acc[i][1]=0ull; }

  for (int dy=-1;dy<=1;dy++){
    int hy = h+dy;
    if (hy<0 || hy>=HH) continue;
    for (int dx=-1;dx<=1;dx++){
      int tap = (dy+1)*3 + (dx+1);
      const float* wt = g_Wt + (size_t)tap*CDIM*CDIM;
      for (int c0=0;c0<CDIM;c0+=8){
        __syncthreads();
        #pragma unroll
        for (int r=0;r<2;r++){
          int idx = tid + r*256;
          int kk = idx>>6, w = idx&63;
          int wx = w+dx;
          Ash[kk][w] = (wx>=0 && wx<WW) ? att[(size_t)(c0+kk)*NPIX + hy*WW + wx] : 0.f;
        }
        #pragma unroll
        for (int r=0;r<4;r++){
          int idx = tid + r*256;
          int kk = idx>>7, cc = idx&127;
          Bsh[kk][cc] = wt[(size_t)(c0+kk)*CDIM + cc];
        }
        __syncthreads();
        #pragma unroll
        for (int kk=0;kk<8;kk++){
          ulonglong2 aj = *(const ulonglong2*)&Ash[kk][tx*4];
          float br[8];
          #pragma unroll
          for (int u=0;u<4;u++) br[u]   = Bsh[kk][ty*4+u];
          #pragma unroll
          for (int u=0;u<4;u++) br[4+u] = Bsh[kk][64+ty*4+u];
          #pragma unroll
          for (int i=0;i<8;i++){
            unsigned long long bpk = pack2(br[i]);
            acc[i][0] = ffma2u(bpk, aj.x, acc[i][0]);
            acc[i][1] = ffma2u(bpk, aj.y, acc[i][1]);
          }
        }
      }
    }
  }
  const float g = gamma[0];
  #pragma unroll
  for (int i=0;i<8;i++){
    int co = (i<4)? (ty*4+i) : (64+ty*4+(i-4));
    float bv = bp[co];
    size_t base = ((size_t)b*CDIM+co)*NPIX + (size_t)h*WW + tx*4;
    float4 s = *(const float4*)&sr[base];
    float4 o;
    o.x = s.x + g*(bv + lo2(acc[i][0]));
    o.y = s.y + g*(bv + hi2(acc[i][0]));
    o.z = s.z + g*(bv + lo2(acc[i][1]));
    o.w = s.w + g*(bv + hi2(acc[i][1]));
    *(float4*)&out[base] = o;
  }
}

// ---------------- launcher ----------------
extern "C" void kernel_launch(void* const* d_in, const int* in_sizes, int n_in,
                              void* d_out, int out_size){
  (void)in_sizes; (void)n_in; (void)out_size;
  const float* sr  =(const float*)d_in[0];
  const float* ctx =(const float*)d_in[1];
  const float* Wq  =(const float*)d_in[2];
  const float* bq  =(const float*)d_in[3];
  const float* Wk  =(const float*)d_in[4];
  const float* bk  =(const float*)d_in[5];
  const float* Wv  =(const float*)d_in[6];
  const float* bv  =(const float*)d_in[7];
  const float* Wp  =(const float*)d_in[8];
  const float* bp  =(const float*)d_in[9];
  const float* gm  =(const float*)d_in[10];
  float* out = (float*)d_out;

  const int SMEM_MMA = 65536 + 512;
  cudaFuncSetAttribute(mma1_kernel, cudaFuncAttributeMaxDynamicSharedMemorySize, SMEM_MMA);
  cudaFuncSetAttribute(mma2_kernel, cudaFuncAttributeMaxDynamicSharedMemorySize, SMEM_MMA);

  conv1x1_kernel<CDIM,0><<<dim3(64,2,BATCH),256>>>(sr,  Wq, bq, NPIX);  // Q bf16 [n][c]
  conv1x1_kernel<CCTX,2><<<dim3(16,2,BATCH),256>>>(ctx, Wk, bk, NS);    // K fp32 [ms][c]
  conv1x1_kernel<CCTX,1><<<dim3(16,2,BATCH),256>>>(ctx, Wv, bv, NS);    // V fp32 [c][ms]
  upsample_last_kernel <<<dim3(HH,BATCH),256>>>();                      // -> g_kh bf16 [m][c]
  upsample_plane_kernel<<<dim3(CDIM,BATCH),256>>>();                    // -> g_vh bf16 [c][m]
  wt_kernel<<<576,256>>>(Wp);
  mma1_kernel<<<dim3(32,32,BATCH),256,SMEM_MMA>>>();
  rinv_kernel<<<64,256>>>();
  mma2_kernel<<<dim3(32,BATCH),256,SMEM_MMA>>>();
  conv3_kernel<<<dim3(HH,BATCH),256>>>(sr, bp, gm, out);
}

// round 15
// speedup vs baseline: 1.2689x; 1.2689x over previous
#include <cuda_runtime.h>
#include <cuda_bf16.h>
#include <cstdint>

#define BATCH 4
#define CDIM 128
#define CCTX 256
#define NPIX 4096
#define HS 32
#define NS 1024
#define HH 64
#define WW 64

// ---------------- scratch (device globals; no allocation) ----------------
__device__ __nv_bfloat16 g_qh[(size_t)BATCH*NPIX*CDIM];   // Q bf16 [b][n][c]
__device__ __nv_bfloat16 g_kh[(size_t)BATCH*NPIX*CDIM];   // K bf16 [b][m][c]
__device__ __nv_bfloat16 g_vh[(size_t)BATCH*CDIM*NPIX];   // V bf16 [b][c][m]
__device__ float g_kt[(size_t)BATCH*NS*CDIM];             // K conv out fp32 [b][ms][c]
__device__ float g_vs[(size_t)BATCH*CDIM*NS];             // V conv out fp32 [b][c][ms]
__device__ float g_att[(size_t)BATCH*CDIM*NPIX];          // attn out fp32 [b][c][n]
__device__ float g_Wt [9*CDIM*CDIM];                      // [tap][ci][co]

// ---------------- helpers ----------------
__device__ __forceinline__ uint32_t smem_u32(const void* p){
  uint32_t a;
  asm("{ .reg .u64 t; cvta.to.shared.u64 t, %1; cvt.u32.u64 %0, t; }" : "=r"(a) : "l"(p));
  return a;
}
__device__ __forceinline__ void cpasync16(void* sdst, const void* gsrc){
  uint32_t d = smem_u32(sdst);
  asm volatile("cp.async.cg.shared.global [%0], [%1], 16;" :: "r"(d), "l"(gsrc) : "memory");
}
#define CP_COMMIT() asm volatile("cp.async.commit_group;" ::: "memory")
#define CP_WAIT0()  asm volatile("cp.async.wait_group 0;" ::: "memory")
#define CP_WAIT1()  asm volatile("cp.async.wait_group 1;" ::: "memory")

// HMMA m16n8k16 bf16 -> fp32
__device__ __forceinline__ void mma16816(float* d, const uint32_t* a, const uint32_t* b){
  asm volatile("mma.sync.aligned.m16n8k16.row.col.f32.bf16.bf16.f32 "
    "{%0,%1,%2,%3}, {%4,%5,%6,%7}, {%8,%9}, {%0,%1,%2,%3};"
    : "+f"(d[0]), "+f"(d[1]), "+f"(d[2]), "+f"(d[3])
    : "r"(a[0]), "r"(a[1]), "r"(a[2]), "r"(a[3]), "r"(b[0]), "r"(b[1]));
}

// swizzled LDS of a bf16 pair: row-major rows of RW bf16 elems, w = pair index
template<int RW>
__device__ __forceinline__ uint32_t ldsw(const __nv_bfloat16* base, int r, int w){
  return *(const uint32_t*)(base + r*RW + 2*(w ^ ((r&7)<<2)));
}

// ---------------- packed fp32 helpers (FFMA2) ----------------
__device__ __forceinline__ unsigned long long pack2(float x){
  unsigned int xi = __float_as_uint(x);
  unsigned long long r;
  asm("mov.b64 %0, {%1, %1};" : "=l"(r) : "r"(xi));
  return r;
}
__device__ __forceinline__ unsigned long long ffma2u(unsigned long long a,
                                                     unsigned long long b,
                                                     unsigned long long c){
  asm("fma.rn.f32x2 %0, %1, %2, %0;" : "+l"(c) : "l"(a), "l"(b));
  return c;
}
__device__ __forceinline__ float lo2(unsigned long long v){ return __uint_as_float((unsigned int)v); }
__device__ __forceinline__ float hi2(unsigned long long v){ return __uint_as_float((unsigned int)(v>>32)); }

// ---------------- 1x1 conv GEMM ----------------
// DST: 0 -> Q bf16 [b][n][c]; 1 -> g_vs fp32 [b][c][ms]; 2 -> g_kt fp32 [b][ms][c]
template<int CI, int DST>
__global__ __launch_bounds__(256) void conv1x1_kernel(
    const float* __restrict__ in, const float* __restrict__ W,
    const float* __restrict__ bias, int Npix)
{
  __shared__ float Ash[16][64];
  __shared__ float Bsh[16][68];
  const int n0 = blockIdx.x*64, co0 = blockIdx.y*64, b = blockIdx.z;
  const int tid = threadIdx.x, tx = tid & 15, ty = tid >> 4;
  const float* inb = in + (size_t)b*CI*Npix;
  float acc[4][4];
  #pragma unroll
  for (int i=0;i<4;i++)
    #pragma unroll
    for (int j=0;j<4;j++) acc[i][j]=0.f;

  for (int k0=0;k0<CI;k0+=16){
    __syncthreads();
    #pragma unroll
    for (int r=0;r<4;r++){
      int idx = tid + r*256;
      Ash[idx>>6][idx&63] = inb[(size_t)(k0+(idx>>6))*Npix + n0 + (idx&63)];
    }
    #pragma unroll
    for (int r=0;r<4;r++){
      int idx = tid + r*256;
      int cc = idx>>4, kk = idx&15;
      Bsh[kk][cc] = W[(size_t)(co0+cc)*CI + k0+kk];
    }
    __syncthreads();
    #pragma unroll
    for (int kk=0;kk<16;kk++){
      float a[4], bb[4];
      #pragma unroll
      for (int u=0;u<4;u++) a[u]=Ash[kk][tx*4+u];
      #pragma unroll
      for (int u=0;u<4;u++) bb[u]=Bsh[kk][ty*4+u];
      #pragma unroll
      for (int i=0;i<4;i++)
        #pragma unroll
        for (int j=0;j<4;j++) acc[i][j] += bb[i]*a[j];
    }
  }
  #pragma unroll
  for (int i=0;i<4;i++){
    int co = co0+ty*4+i;
    float bi = bias[co];
    #pragma unroll
    for (int j=0;j<4;j++){
      int n = n0+tx*4+j;
      float v = acc[i][j]+bi;
      if (DST==0)      g_qh[((size_t)b*NPIX + n)*CDIM + co] = __float2bfloat16(v);
      else if (DST==1) g_vs[((size_t)b*CDIM + co)*NS + n] = v;
      else             g_kt[((size_t)b*NS + n)*CDIM + co] = v;
    }
  }
}

// ---------------- bilinear 2x upsample helpers ----------------
__device__ __forceinline__ void bsrc(int o, int &i0, int &i1, float &w1){
  float s = 0.5f*(float)o - 0.25f;
  float f = floorf(s);
  w1 = s - f;
  int i = (int)f;
  i0 = i < 0 ? 0 : i;
  i1 = (i+1 > HS-1) ? (HS-1) : (i+1);
}

// V: [c][ms] fp32 -> [c][m] bf16
__global__ void upsample_plane_kernel(){
  __shared__ float sch[HS*HS];
  int c = blockIdx.x, b = blockIdx.y;
  const float* src = g_vs + ((size_t)b*CDIM + c)*NS;
  for (int i=threadIdx.x;i<NS;i+=256) sch[i]=src[i];
  __syncthreads();
  __nv_bfloat16* dst = g_vh + ((size_t)b*CDIM + c)*NPIX;
  for (int p=threadIdx.x;p<NPIX;p+=256){
    int h=p>>6, w=p&63;
    int y0,y1,x0,x1; float wy,wx;
    bsrc(h,y0,y1,wy); bsrc(w,x0,x1,wx);
    float v = (1.f-wy)*((1.f-wx)*sch[y0*HS+x0]+wx*sch[y0*HS+x1])
            +      wy *((1.f-wx)*sch[y1*HS+x0]+wx*sch[y1*HS+x1]);
    dst[p] = __float2bfloat16(v);
  }
}

// K: [ms][c] fp32 -> [m][c] bf16 (smem-cached rows, coalesced)
__global__ __launch_bounds__(256) void upsample_last_kernel(){
  __shared__ float rows[2][HS][CDIM];   // 32KB
  const int h = blockIdx.x, b = blockIdx.y, tid = threadIdx.x;
  int y0,y1; float wy; bsrc(h,y0,y1,wy);
  const float* src = g_kt + (size_t)b*NS*CDIM;
  const float4* s0 = (const float4*)(src + (size_t)y0*HS*CDIM);
  const float4* s1 = (const float4*)(src + (size_t)y1*HS*CDIM);
  float4* r0 = (float4*)&rows[0][0][0];
  float4* r1 = (float4*)&rows[1][0][0];
  #pragma unroll
  for (int i=0;i<4;i++){
    r0[tid + i*256] = s0[tid + i*256];
    r1[tid + i*256] = s1[tid + i*256];
  }
  __syncthreads();
  __nv_bfloat16* dst = g_kh + ((size_t)b*NPIX + (size_t)h*WW)*CDIM;
  const int c = tid & 127, w0 = tid >> 7;
  for (int w=w0; w<WW; w+=2){
    int x0,x1; float wx; bsrc(w,x0,x1,wx);
    float v = (1.f-wy)*((1.f-wx)*rows[0][x0][c] + wx*rows[0][x1][c])
            +      wy *((1.f-wx)*rows[1][x0][c] + wx*rows[1][x1][c]);
    dst[(size_t)w*CDIM + c] = __float2bfloat16(v);
  }
}

// ---------------- fused flash attention: O[n][c] = softmax_m(Q.K^T) . V^T --------------
// grid (32 n-tiles, B). block 256 = 8 warps; warp w owns n rows [w*16, w*16+16).
// smem: Qs 32KB | K bufs 2x32KB @32K,64K | V bufs 2x32KB @96K,128K  (160KB total)
// epilogue reuses @32K as 128x132 fp32 O staging.
__global__ __launch_bounds__(256,1) void flash_kernel(){
  extern __shared__ char smem[];
  __nv_bfloat16* Qs = (__nv_bfloat16*)smem;
  const int tid = threadIdx.x, lane = tid&31, wid = tid>>5;
  const int tig = lane&3, g = lane>>2;
  const int n0 = blockIdx.x*128, b = blockIdx.y;

  // Q tile resident
  const uint4* gq = (const uint4*)(g_qh + ((size_t)b*NPIX + n0)*CDIM);
  #pragma unroll
  for (int r=0;r<8;r++){
    int i = tid + r*256;
    int row = i>>4, seg = i&15;
    cpasync16(Qs + row*128 + ((seg ^ (row&7))<<3), gq + i);
  }
  CP_COMMIT();

  const uint4* gk = (const uint4*)(g_kh + (size_t)b*NPIX*CDIM);   // rows m, 16 uint4/row
  const uint4* gv = (const uint4*)(g_vh + (size_t)b*CDIM*NPIX);   // rows c, 512 uint4/row

  auto stage = [&](int mt, int buf){
    __nv_bfloat16* Kb = (__nv_bfloat16*)(smem + 32768 + buf*32768);
    __nv_bfloat16* Vb = (__nv_bfloat16*)(smem + 98304 + buf*32768);
    #pragma unroll
    for (int r=0;r<8;r++){
      int i = tid + r*256;
      int row = i>>4, seg = i&15;
      int so = row*128 + ((seg ^ (row&7))<<3);
      cpasync16(Kb + so, gk + (size_t)(mt*128 + row)*16 + seg);
      cpasync16(Vb + so, gv + (size_t)row*512 + mt*16 + seg);
    }
    CP_COMMIT();
  };

  float oacc[16][4];
  #pragma unroll
  for (int tj=0;tj<16;tj++)
    #pragma unroll
    for (int u=0;u<4;u++) oacc[tj][u]=0.f;
  float rs0 = 0.f, rs1 = 0.f;

  stage(0,0);
  stage(1,1);

  int buf = 0;
  const int rA = wid*16 + g;
  for (int mt=0; mt<32; mt++){
    if (mt==31) CP_WAIT0(); else CP_WAIT1();
    __syncthreads();
    const __nv_bfloat16* Kb = (const __nv_bfloat16*)(smem + 32768 + buf*32768);
    const __nv_bfloat16* Vb = (const __nv_bfloat16*)(smem + 98304 + buf*32768);

    // S = Q . K^T  (warp: 16n x 128m)
    float sacc[16][4];
    #pragma unroll
    for (int tj=0;tj<16;tj++)
      #pragma unroll
      for (int u=0;u<4;u++) sacc[tj][u]=0.f;
    #pragma unroll
    for (int ks=0;ks<8;ks++){
      const int w0 = ks*8 + tig;
      uint32_t aF[4];
      aF[0] = ldsw<128>(Qs, rA,   w0);
      aF[1] = ldsw<128>(Qs, rA+8, w0);
      aF[2] = ldsw<128>(Qs, rA,   w0+4);
      aF[3] = ldsw<128>(Qs, rA+8, w0+4);
      #pragma unroll
      for (int tj=0;tj<16;tj++){
        uint32_t bF[2];
        int rr = tj*8 + g;
        bF[0] = ldsw<128>(Kb, rr, w0);
        bF[1] = ldsw<128>(Kb, rr, w0+4);
        mma16816(sacc[tj], aF, bF);
      }
    }

    // P = exp(S): rowsum + pack acc->A fragments (FA2 identity)
    uint32_t aP[8][4];
    #pragma unroll
    for (int kk=0;kk<8;kk++){
      float e0=__expf(sacc[2*kk][0]),   e1=__expf(sacc[2*kk][1]);
      float e2=__expf(sacc[2*kk][2]),   e3=__expf(sacc[2*kk][3]);
      float f0=__expf(sacc[2*kk+1][0]), f1=__expf(sacc[2*kk+1][1]);
      float f2=__expf(sacc[2*kk+1][2]), f3=__expf(sacc[2*kk+1][3]);
      rs0 += e0+e1+f0+f1;
      rs1 += e2+e3+f2+f3;
      __nv_bfloat162 t;
      t=__floats2bfloat162_rn(e0,e1); aP[kk][0]=*(uint32_t*)&t;
      t=__floats2bfloat162_rn(e2,e3); aP[kk][1]=*(uint32_t*)&t;
      t=__floats2bfloat162_rn(f0,f1); aP[kk][2]=*(uint32_t*)&t;
      t=__floats2bfloat162_rn(f2,f3); aP[kk][3]=*(uint32_t*)&t;
    }

    // O += P . V^T  (warp: 16n x 128c, k = 128m from registers)
    #pragma unroll
    for (int kk=0;kk<8;kk++){
      const int w0 = kk*8 + tig;
      #pragma unroll
      for (int tj=0;tj<16;tj++){
        uint32_t bF[2];
        int rr = tj*8 + g;
        bF[0] = ldsw<128>(Vb, rr, w0);
        bF[1] = ldsw<128>(Vb, rr, w0+4);
        mma16816(oacc[tj], aP[kk], bF);
      }
    }

    __syncthreads();
    if (mt+2 < 32) stage(mt+2, buf);
    buf ^= 1;
  }

  // rowsum reduce across tig (cols)
  rs0 += __shfl_xor_sync(0xffffffffu, rs0, 1);
  rs0 += __shfl_xor_sync(0xffffffffu, rs0, 2);
  rs1 += __shfl_xor_sync(0xffffffffu, rs1, 1);
  rs1 += __shfl_xor_sync(0xffffffffu, rs1, 2);
  const float ri0 = 1.f/rs0, ri1 = 1.f/rs1;

  // stage O to smem [128n][132] fp32, then write g_att [c][n] coalesced
  __syncthreads();
  float* Osm = (float*)(smem + 32768);
  #pragma unroll
  for (int tj=0;tj<16;tj++){
    int c = tj*8 + 2*tig;
    *(float2*)&Osm[(size_t)rA*132 + c]     = make_float2(oacc[tj][0]*ri0, oacc[tj][1]*ri0);
    *(float2*)&Osm[(size_t)(rA+8)*132 + c] = make_float2(oacc[tj][2]*ri1, oacc[tj][3]*ri1);
  }
  __syncthreads();
  const int c = tid>>1, nh = (tid&1)*64;
  float* dst = g_att + ((size_t)b*CDIM + c)*NPIX + n0 + nh;
  #pragma unroll
  for (int j=0;j<16;j++){
    float4 v;
    v.x = Osm[(size_t)(nh+4*j+0)*132 + c];
    v.y = Osm[(size_t)(nh+4*j+1)*132 + c];
    v.z = Osm[(size_t)(nh+4*j+2)*132 + c];
    v.w = Osm[(size_t)(nh+4*j+3)*132 + c];
    *(float4*)&dst[4*j] = v;
  }
}

// ---------------- Wp transpose to [tap][ci][co] ----------------
__global__ void wt_kernel(const float* __restrict__ Wp){
  int i = blockIdx.x*256+threadIdx.x;
  if (i < 9*CDIM*CDIM){
    int tap = i/(CDIM*CDIM), r = i%(CDIM*CDIM);
    int ci = r>>7, co = r&127;
    g_Wt[i] = Wp[((size_t)co*CDIM + ci)*9 + tap];
  }
}

// ---------------- final: out = sr + gamma*(bp + conv3x3(att)) ----------------
__global__ __launch_bounds__(256) void conv3_kernel(
  const float* __restrict__ sr, const float* __restrict__ bp,
  const float* __restrict__ gamma, float* __restrict__ out)
{
  __shared__ float Ash[8][64];
  __shared__ float Bsh[8][128];
  const int h = blockIdx.x, b = blockIdx.y;
  const int tid=threadIdx.x, tx=tid&15, ty=tid>>4;
  const float* att = g_att + (size_t)b*CDIM*NPIX;
  unsigned long long acc[8][2];
  #pragma unroll
  for (int i=0;i<8;i++){ acc[i][0]=0ull; acc[i][1]=0ull; }

  for (int dy=-1;dy<=1;dy++){
    int hy = h+dy;
    if (hy<0 || hy>=HH) continue;
    for (int dx=-1;dx<=1;dx++){
      int tap = (dy+1)*3 + (dx+1);
      const float* wt = g_Wt + (size_t)tap*CDIM*CDIM;
      for (int c0=0;c0<CDIM;c0+=8){
        __syncthreads();
        #pragma unroll
        for (int r=0;r<2;r++){
          int idx = tid + r*256;
          int kk = idx>>6, w = idx&63;
          int wx = w+dx;
          Ash[kk][w] = (wx>=0 && wx<WW) ? att[(size_t)(c0+kk)*NPIX + hy*WW + wx] : 0.f;
        }
        #pragma unroll
        for (int r=0;r<4;r++){
          int idx = tid + r*256;
          int kk = idx>>7, cc = idx&127;
          Bsh[kk][cc] = wt[(size_t)(c0+kk)*CDIM + cc];
        }
        __syncthreads();
        #pragma unroll
        for (int kk=0;kk<8;kk++){
          ulonglong2 aj = *(const ulonglong2*)&Ash[kk][tx*4];
          float br[8];
          #pragma unroll
          for (int u=0;u<4;u++) br[u]   = Bsh[kk][ty*4+u];
          #pragma unroll
          for (int u=0;u<4;u++) br[4+u] = Bsh[kk][64+ty*4+u];
          #pragma unroll
          for (int i=0;i<8;i++){
            unsigned long long bpk = pack2(br[i]);
            acc[i][0] = ffma2u(bpk, aj.x, acc[i][0]);
            acc[i][1] = ffma2u(bpk, aj.y, acc[i][1]);
          }
        }
      }
    }
  }
  const float g = gamma[0];
  #pragma unroll
  for (int i=0;i<8;i++){
    int co = (i<4)? (ty*4+i) : (64+ty*4+(i-4));
    float bv = bp[co];
    size_t base = ((size_t)b*CDIM+co)*NPIX + (size_t)h*WW + tx*4;
    float4 s = *(const float4*)&sr[base];
    float4 o;
    o.x = s.x + g*(bv + lo2(acc[i][0]));
    o.y = s.y + g*(bv + hi2(acc[i][0]));
    o.z = s.z + g*(bv + lo2(acc[i][1]));
    o.w = s.w + g*(bv + hi2(acc[i][1]));
    *(float4*)&out[base] = o;
  }
}

// ---------------- launcher ----------------
extern "C" void kernel_launch(void* const* d_in, const int* in_sizes, int n_in,
                              void* d_out, int out_size){
  (void)in_sizes; (void)n_in; (void)out_size;
  const float* sr  =(const float*)d_in[0];
  const float* ctx =(const float*)d_in[1];
  const float* Wq  =(const float*)d_in[2];
  const float* bq  =(const float*)d_in[3];
  const float* Wk  =(const float*)d_in[4];
  const float* bk  =(const float*)d_in[5];
  const float* Wv  =(const float*)d_in[6];
  const float* bv  =(const float*)d_in[7];
  const float* Wp  =(const float*)d_in[8];
  const float* bp  =(const float*)d_in[9];
  const float* gm  =(const float*)d_in[10];
  float* out = (float*)d_out;

  const int SMEM_FLASH = 163840;  // 160KB
  cudaFuncSetAttribute(flash_kernel, cudaFuncAttributeMaxDynamicSharedMemorySize, SMEM_FLASH);

  conv1x1_kernel<CDIM,0><<<dim3(64,2,BATCH),256>>>(sr,  Wq, bq, NPIX);  // Q bf16 [n][c]
  conv1x1_kernel<CCTX,2><<<dim3(16,2,BATCH),256>>>(ctx, Wk, bk, NS);    // K fp32 [ms][c]
  conv1x1_kernel<CCTX,1><<<dim3(16,2,BATCH),256>>>(ctx, Wv, bv, NS);    // V fp32 [c][ms]
  upsample_last_kernel <<<dim3(HH,BATCH),256>>>();                      // -> g_kh bf16 [m][c]
  upsample_plane_kernel<<<dim3(CDIM,BATCH),256>>>();                    // -> g_vh bf16 [c][m]
  wt_kernel<<<576,256>>>(Wp);
  flash_kernel<<<dim3(32,BATCH),256,SMEM_FLASH>>>();
  conv3_kernel<<<dim3(HH,BATCH),256>>>(sr, bp, gm, out);
}

// round 16
// speedup vs baseline: 2.0069x; 1.5816x over previous
#include <cuda_runtime.h>
#include <cuda_bf16.h>
#include <cstdint>

#define BATCH 4
#define CDIM 128
#define CCTX 256
#define NPIX 4096
#define HS 32
#define NS 1024
#define HH 64
#define WW 64

// ---------------- scratch (device globals; no allocation) ----------------
__device__ __nv_bfloat16 g_qh[(size_t)BATCH*NPIX*CDIM];   // Q bf16 [b][n][c]
__device__ __nv_bfloat16 g_kh[(size_t)BATCH*NPIX*CDIM];   // K bf16 [b][m][c]
__device__ __nv_bfloat16 g_vh[(size_t)BATCH*CDIM*NPIX];   // V bf16 [b][c][m]
__device__ float g_kt[(size_t)BATCH*NS*CDIM];             // K conv out fp32 [b][ms][c]
__device__ float g_vs[(size_t)BATCH*CDIM*NS];             // V conv out fp32 [b][c][ms]
__device__ __nv_bfloat16 g_ah[(size_t)BATCH*NPIX*CDIM];   // attn out bf16 [b][n][c]
__device__ __nv_bfloat16 g_wh[9*CDIM*CDIM];               // Wp bf16 [tap][co][ci]

// ---------------- helpers ----------------
__device__ __forceinline__ uint32_t smem_u32(const void* p){
  uint32_t a;
  asm("{ .reg .u64 t; cvta.to.shared.u64 t, %1; cvt.u32.u64 %0, t; }" : "=r"(a) : "l"(p));
  return a;
}
__device__ __forceinline__ void cpasync16(void* sdst, const void* gsrc){
  uint32_t d = smem_u32(sdst);
  asm volatile("cp.async.cg.shared.global [%0], [%1], 16;" :: "r"(d), "l"(gsrc) : "memory");
}
#define CP_COMMIT() asm volatile("cp.async.commit_group;" ::: "memory")
#define CP_WAIT0()  asm volatile("cp.async.wait_group 0;" ::: "memory")
#define CP_WAIT1()  asm volatile("cp.async.wait_group 1;" ::: "memory")

// HMMA m16n8k16 bf16 -> fp32
__device__ __forceinline__ void mma16816(float* d, const uint32_t* a, const uint32_t* b){
  asm volatile("mma.sync.aligned.m16n8k16.row.col.f32.bf16.bf16.f32 "
    "{%0,%1,%2,%3}, {%4,%5,%6,%7}, {%8,%9}, {%0,%1,%2,%3};"
    : "+f"(d[0]), "+f"(d[1]), "+f"(d[2]), "+f"(d[3])
    : "r"(a[0]), "r"(a[1]), "r"(a[2]), "r"(a[3]), "r"(b[0]), "r"(b[1]));
}

// swizzled LDS of a bf16 pair: row-major rows of RW bf16 elems, w = pair index
template<int RW>
__device__ __forceinline__ uint32_t ldsw(const __nv_bfloat16* base, int r, int w){
  return *(const uint32_t*)(base + r*RW + 2*(w ^ ((r&7)<<2)));
}

// ---------------- 1x1 conv GEMM ----------------
// DST: 0 -> Q bf16 [b][n][c]; 1 -> g_vs fp32 [b][c][ms]; 2 -> g_kt fp32 [b][ms][c]
template<int CI, int DST>
__global__ __launch_bounds__(256) void conv1x1_kernel(
    const float* __restrict__ in, const float* __restrict__ W,
    const float* __restrict__ bias, int Npix)
{
  __shared__ float Ash[16][64];
  __shared__ float Bsh[16][68];
  const int n0 = blockIdx.x*64, co0 = blockIdx.y*64, b = blockIdx.z;
  const int tid = threadIdx.x, tx = tid & 15, ty = tid >> 4;
  const float* inb = in + (size_t)b*CI*Npix;
  float acc[4][4];
  #pragma unroll
  for (int i=0;i<4;i++)
    #pragma unroll
    for (int j=0;j<4;j++) acc[i][j]=0.f;

  for (int k0=0;k0<CI;k0+=16){
    __syncthreads();
    #pragma unroll
    for (int r=0;r<4;r++){
      int idx = tid + r*256;
      Ash[idx>>6][idx&63] = inb[(size_t)(k0+(idx>>6))*Npix + n0 + (idx&63)];
    }
    #pragma unroll
    for (int r=0;r<4;r++){
      int idx = tid + r*256;
      int cc = idx>>4, kk = idx&15;
      Bsh[kk][cc] = W[(size_t)(co0+cc)*CI + k0+kk];
    }
    __syncthreads();
    #pragma unroll
    for (int kk=0;kk<16;kk++){
      float a[4], bb[4];
      #pragma unroll
      for (int u=0;u<4;u++) a[u]=Ash[kk][tx*4+u];
      #pragma unroll
      for (int u=0;u<4;u++) bb[u]=Bsh[kk][ty*4+u];
      #pragma unroll
      for (int i=0;i<4;i++)
        #pragma unroll
        for (int j=0;j<4;j++) acc[i][j] += bb[i]*a[j];
    }
  }
  #pragma unroll
  for (int i=0;i<4;i++){
    int co = co0+ty*4+i;
    float bi = bias[co];
    #pragma unroll
    for (int j=0;j<4;j++){
      int n = n0+tx*4+j;
      float v = acc[i][j]+bi;
      if (DST==0)      g_qh[((size_t)b*NPIX + n)*CDIM + co] = __float2bfloat16(v);
      else if (DST==1) g_vs[((size_t)b*CDIM + co)*NS + n] = v;
      else             g_kt[((size_t)b*NS + n)*CDIM + co] = v;
    }
  }
}

// ---------------- bilinear 2x upsample helpers ----------------
__device__ __forceinline__ void bsrc(int o, int &i0, int &i1, float &w1){
  float s = 0.5f*(float)o - 0.25f;
  float f = floorf(s);
  w1 = s - f;
  int i = (int)f;
  i0 = i < 0 ? 0 : i;
  i1 = (i+1 > HS-1) ? (HS-1) : (i+1);
}

// V: [c][ms] fp32 -> [c][m] bf16
__global__ void upsample_plane_kernel(){
  __shared__ float sch[HS*HS];
  int c = blockIdx.x, b = blockIdx.y;
  const float* src = g_vs + ((size_t)b*CDIM + c)*NS;
  for (int i=threadIdx.x;i<NS;i+=256) sch[i]=src[i];
  __syncthreads();
  __nv_bfloat16* dst = g_vh + ((size_t)b*CDIM + c)*NPIX;
  for (int p=threadIdx.x;p<NPIX;p+=256){
    int h=p>>6, w=p&63;
    int y0,y1,x0,x1; float wy,wx;
    bsrc(h,y0,y1,wy); bsrc(w,x0,x1,wx);
    float v = (1.f-wy)*((1.f-wx)*sch[y0*HS+x0]+wx*sch[y0*HS+x1])
            +      wy *((1.f-wx)*sch[y1*HS+x0]+wx*sch[y1*HS+x1]);
    dst[p] = __float2bfloat16(v);
  }
}

// K: [ms][c] fp32 -> [m][c] bf16 (smem-cached rows, coalesced)
__global__ __launch_bounds__(256) void upsample_last_kernel(){
  __shared__ float rows[2][HS][CDIM];   // 32KB
  const int h = blockIdx.x, b = blockIdx.y, tid = threadIdx.x;
  int y0,y1; float wy; bsrc(h,y0,y1,wy);
  const float* src = g_kt + (size_t)b*NS*CDIM;
  const float4* s0 = (const float4*)(src + (size_t)y0*HS*CDIM);
  const float4* s1 = (const float4*)(src + (size_t)y1*HS*CDIM);
  float4* r0 = (float4*)&rows[0][0][0];
  float4* r1 = (float4*)&rows[1][0][0];
  #pragma unroll
  for (int i=0;i<4;i++){
    r0[tid + i*256] = s0[tid + i*256];
    r1[tid + i*256] = s1[tid + i*256];
  }
  __syncthreads();
  __nv_bfloat16* dst = g_kh + ((size_t)b*NPIX + (size_t)h*WW)*CDIM;
  const int c = tid & 127, w0 = tid >> 7;
  for (int w=w0; w<WW; w+=2){
    int x0,x1; float wx; bsrc(w,x0,x1,wx);
    float v = (1.f-wy)*((1.f-wx)*rows[0][x0][c] + wx*rows[0][x1][c])
            +      wy *((1.f-wx)*rows[1][x0][c] + wx*rows[1][x1][c]);
    dst[(size_t)w*CDIM + c] = __float2bfloat16(v);
  }
}

// ---------------- fused flash attention: O[n][c] = softmax_m(Q.K^T) . V^T --------------
// grid (32 n-tiles, B). block 256 = 8 warps; warp w owns n rows [w*16, w*16+16).
// smem: Qs 32KB | K bufs 2x32KB @32K,64K | V bufs 2x32KB @96K,128K  (160KB total)
// epilogue reuses @32K as 128x136 bf16 O staging -> g_ah [n][c].
__global__ __launch_bounds__(256,1) void flash_kernel(){
  extern __shared__ char smem[];
  __nv_bfloat16* Qs = (__nv_bfloat16*)smem;
  const int tid = threadIdx.x, lane = tid&31, wid = tid>>5;
  const int tig = lane&3, g = lane>>2;
  const int n0 = blockIdx.x*128, b = blockIdx.y;

  // Q tile resident
  const uint4* gq = (const uint4*)(g_qh + ((size_t)b*NPIX + n0)*CDIM);
  #pragma unroll
  for (int r=0;r<8;r++){
    int i = tid + r*256;
    int row = i>>4, seg = i&15;
    cpasync16(Qs + row*128 + ((seg ^ (row&7))<<3), gq + i);
  }
  CP_COMMIT();

  const uint4* gk = (const uint4*)(g_kh + (size_t)b*NPIX*CDIM);   // rows m, 16 uint4/row
  const uint4* gv = (const uint4*)(g_vh + (size_t)b*CDIM*NPIX);   // rows c, 512 uint4/row

  auto stage = [&](int mt, int buf){
    __nv_bfloat16* Kb = (__nv_bfloat16*)(smem + 32768 + buf*32768);
    __nv_bfloat16* Vb = (__nv_bfloat16*)(smem + 98304 + buf*32768);
    #pragma unroll
    for (int r=0;r<8;r++){
      int i = tid + r*256;
      int row = i>>4, seg = i&15;
      int so = row*128 + ((seg ^ (row&7))<<3);
      cpasync16(Kb + so, gk + (size_t)(mt*128 + row)*16 + seg);
      cpasync16(Vb + so, gv + (size_t)row*512 + mt*16 + seg);
    }
    CP_COMMIT();
  };

  float oacc[16][4];
  #pragma unroll
  for (int tj=0;tj<16;tj++)
    #pragma unroll
    for (int u=0;u<4;u++) oacc[tj][u]=0.f;
  float rs0 = 0.f, rs1 = 0.f;

  stage(0,0);
  stage(1,1);

  int buf = 0;
  const int rA = wid*16 + g;
  for (int mt=0; mt<32; mt++){
    if (mt==31) CP_WAIT0(); else CP_WAIT1();
    __syncthreads();
    const __nv_bfloat16* Kb = (const __nv_bfloat16*)(smem + 32768 + buf*32768);
    const __nv_bfloat16* Vb = (const __nv_bfloat16*)(smem + 98304 + buf*32768);

    // S = Q . K^T  (warp: 16n x 128m)
    float sacc[16][4];
    #pragma unroll
    for (int tj=0;tj<16;tj++)
      #pragma unroll
      for (int u=0;u<4;u++) sacc[tj][u]=0.f;
    #pragma unroll
    for (int ks=0;ks<8;ks++){
      const int w0 = ks*8 + tig;
      uint32_t aF[4];
      aF[0] = ldsw<128>(Qs, rA,   w0);
      aF[1] = ldsw<128>(Qs, rA+8, w0);
      aF[2] = ldsw<128>(Qs, rA,   w0+4);
      aF[3] = ldsw<128>(Qs, rA+8, w0+4);
      #pragma unroll
      for (int tj=0;tj<16;tj++){
        uint32_t bF[2];
        int rr = tj*8 + g;
        bF[0] = ldsw<128>(Kb, rr, w0);
        bF[1] = ldsw<128>(Kb, rr, w0+4);
        mma16816(sacc[tj], aF, bF);
      }
    }

    // P = exp(S): rowsum + pack acc->A fragments (FA2 identity)
    uint32_t aP[8][4];
    #pragma unroll
    for (int kk=0;kk<8;kk++){
      float e0=__expf(sacc[2*kk][0]),   e1=__expf(sacc[2*kk][1]);
      float e2=__expf(sacc[2*kk][2]),   e3=__expf(sacc[2*kk][3]);
      float f0=__expf(sacc[2*kk+1][0]), f1=__expf(sacc[2*kk+1][1]);
      float f2=__expf(sacc[2*kk+1][2]), f3=__expf(sacc[2*kk+1][3]);
      rs0 += e0+e1+f0+f1;
      rs1 += e2+e3+f2+f3;
      __nv_bfloat162 t;
      t=__floats2bfloat162_rn(e0,e1); aP[kk][0]=*(uint32_t*)&t;
      t=__floats2bfloat162_rn(e2,e3); aP[kk][1]=*(uint32_t*)&t;
      t=__floats2bfloat162_rn(f0,f1); aP[kk][2]=*(uint32_t*)&t;
      t=__floats2bfloat162_rn(f2,f3); aP[kk][3]=*(uint32_t*)&t;
    }

    // O += P . V^T  (warp: 16n x 128c, k = 128m from registers)
    #pragma unroll
    for (int kk=0;kk<8;kk++){
      const int w0 = kk*8 + tig;
      #pragma unroll
      for (int tj=0;tj<16;tj++){
        uint32_t bF[2];
        int rr = tj*8 + g;
        bF[0] = ldsw<128>(Vb, rr, w0);
        bF[1] = ldsw<128>(Vb, rr, w0+4);
        mma16816(oacc[tj], aP[kk], bF);
      }
    }

    __syncthreads();
    if (mt+2 < 32) stage(mt+2, buf);
    buf ^= 1;
  }

  // rowsum reduce across tig (cols)
  rs0 += __shfl_xor_sync(0xffffffffu, rs0, 1);
  rs0 += __shfl_xor_sync(0xffffffffu, rs0, 2);
  rs1 += __shfl_xor_sync(0xffffffffu, rs1, 1);
  rs1 += __shfl_xor_sync(0xffffffffu, rs1, 2);
  const float ri0 = 1.f/rs0, ri1 = 1.f/rs1;

  // stage O to smem as bf16 [128][136], then write g_ah [n][c] coalesced (256B rows)
  __syncthreads();
  __nv_bfloat16* Osm = (__nv_bfloat16*)(smem + 32768);
  #pragma unroll
  for (int tj=0;tj<16;tj++){
    int c = tj*8 + 2*tig;
    __nv_bfloat162 t0 = __floats2bfloat162_rn(oacc[tj][0]*ri0, oacc[tj][1]*ri0);
    __nv_bfloat162 t1 = __floats2bfloat162_rn(oacc[tj][2]*ri1, oacc[tj][3]*ri1);
    *(uint32_t*)&Osm[(size_t)rA*136 + c]     = *(uint32_t*)&t0;
    *(uint32_t*)&Osm[(size_t)(rA+8)*136 + c] = *(uint32_t*)&t1;
  }
  __syncthreads();
  const int row = tid>>1, off = (tid&1)*64;
  const uint4* srow = (const uint4*)&Osm[(size_t)row*136 + off];
  uint4* drow = (uint4*)(g_ah + ((size_t)b*NPIX + n0 + row)*CDIM + off);
  #pragma unroll
  for (int j=0;j<8;j++) drow[j] = srow[j];
}

// ---------------- Wp -> bf16 [tap][co][ci] ----------------
__global__ void wt_kernel(const float* __restrict__ Wp){
  int i = blockIdx.x*256+threadIdx.x;
  if (i < 9*CDIM*CDIM){
    int tap = i>>14, r = i&16383;
    int co = r>>7, ci = r&127;
    g_wh[i] = __float2bfloat16(Wp[((size_t)co*CDIM + ci)*9 + tap]);
  }
}

// ---------------- conv3x3 as per-tap HMMA implicit GEMM + residual ----------------
// grid (32 = HH/2 row-pairs, B). block 256 = 8 warps; warp tile 32px x 64co.
// smem: Att [4][66][128] bf16 (67584B, swizzled, zero halo) | W bufs 2x32KB @67584
// epilogue reuses Att region as [128][132] fp32 staging.
__global__ __launch_bounds__(256,1) void conv3_kernel(
  const float* __restrict__ sr, const float* __restrict__ bp,
  const float* __restrict__ gamma, float* __restrict__ out)
{
  extern __shared__ char smem[];
  __nv_bfloat16* Att = (__nv_bfloat16*)smem;
  const int tid = threadIdx.x, lane = tid&31, wid = tid>>5;
  const int tig = lane&3, g = lane>>2;
  const int wr = wid&3, wc = wid>>2;
  const int h0 = blockIdx.x*2, b = blockIdx.y;
  const uint4 z = make_uint4(0,0,0,0);

  // zero halo columns (w=0 and w=65 of each of 4 row-lines)
  if (tid < 128){
    int r = tid>>5, which = (tid>>4)&1, seg = tid&15;
    int rlin = r*66 + (which ? 65 : 0);
    *(uint4*)(Att + rlin*128 + ((seg ^ (rlin&7))<<3)) = z;
  }
  // att rows h0-1..h0+2 (cp.async valid rows, zero OOB rows)
  const __nv_bfloat16* gatt = g_ah + (size_t)b*NPIX*CDIM;
  #pragma unroll
  for (int r=0;r<4;r++){
    int hy = h0 - 1 + r;
    bool valid = (hy>=0 && hy<HH);
    #pragma unroll
    for (int it=0; it<4; it++){
      int i = tid + it*256;           // 0..1023
      int w = i>>4, seg = i&15;
      int rlin = r*66 + w + 1;
      void* dst = Att + rlin*128 + ((seg ^ (rlin&7))<<3);
      if (valid) cpasync16(dst, (const uint4*)(gatt + ((size_t)hy*WW + w)*CDIM) + seg);
      else      *(uint4*)dst = z;
    }
  }
  CP_COMMIT();

  auto wstage = [&](int tap, int bufw){
    __nv_bfloat16* Wb = (__nv_bfloat16*)(smem + 67584 + bufw*32768);
    const uint4* src = (const uint4*)(g_wh + (size_t)tap*CDIM*CDIM);
    #pragma unroll
    for (int rr=0;rr<8;rr++){
      int i = tid + rr*256;
      int row = i>>4, seg = i&15;
      cpasync16(Wb + row*128 + ((seg ^ (row&7))<<3), src + (size_t)row*16 + seg);
    }
    CP_COMMIT();
  };
  wstage(0,0);
  wstage(1,1);

  float acc[2][8][4];
  #pragma unroll
  for (int ti=0;ti<2;ti++)
    #pragma unroll
    for (int tj=0;tj<8;tj++)
      #pragma unroll
      for (int u=0;u<4;u++) acc[ti][tj][u]=0.f;

  int buf = 0;
  for (int tap=0; tap<9; tap++){
    if (tap==8) CP_WAIT0(); else CP_WAIT1();
    __syncthreads();
    const __nv_bfloat16* Wb = (const __nv_bfloat16*)(smem + 67584 + buf*32768);
    const int dy = tap/3 - 1, dx = tap%3 - 1;
    #pragma unroll
    for (int ks=0;ks<8;ks++){
      const int w0 = ks*8 + tig;
      uint32_t aF[2][4];
      #pragma unroll
      for (int ti=0;ti<2;ti++){
        int p = wr*32 + ti*16 + g;
        int rl  = ((p>>6)+1+dy)*66 + (p&63) + dx + 1;
        int rl2 = rl + 8;   // p+8 stays in same image row (16-aligned chunks)
        aF[ti][0] = ldsw<128>(Att, rl,  w0);
        aF[ti][1] = ldsw<128>(Att, rl2, w0);
        aF[ti][2] = ldsw<128>(Att, rl,  w0+4);
        aF[ti][3] = ldsw<128>(Att, rl2, w0+4);
      }
      #pragma unroll
      for (int tj=0;tj<8;tj++){
        int rr = wc*64 + tj*8 + g;
        uint32_t bF[2];
        bF[0] = ldsw<128>(Wb, rr, w0);
        bF[1] = ldsw<128>(Wb, rr, w0+4);
        #pragma unroll
        for (int ti=0;ti<2;ti++)
          mma16816(acc[ti][tj], aF[ti], bF);
      }
    }
    __syncthreads();
    if (tap+2 < 9) wstage(tap+2, buf);
    buf ^= 1;
  }

  // epilogue: gamma*(bp+acc) staged [128px][132] fp32, then out = sr + ... coalesced
  const float gm = gamma[0];
  float* Osm = (float*)smem;
  #pragma unroll
  for (int ti=0;ti<2;ti++){
    int p = wr*32 + ti*16 + g;
    #pragma unroll
    for (int tj=0;tj<8;tj++){
      int co = wc*64 + tj*8 + 2*tig;
      float b0 = __ldg(bp+co), b1 = __ldg(bp+co+1);
      Osm[(size_t)p*132 + co]       = gm*(b0 + acc[ti][tj][0]);
      Osm[(size_t)p*132 + co+1]     = gm*(b1 + acc[ti][tj][1]);
      Osm[(size_t)(p+8)*132 + co]   = gm*(b0 + acc[ti][tj][2]);
      Osm[(size_t)(p+8)*132 + co+1] = gm*(b1 + acc[ti][tj][3]);
    }
  }
  __syncthreads();
  const int co = tid>>1, off = (tid&1)*64;
  size_t base = ((size_t)b*CDIM + co)*NPIX + (size_t)h0*WW + off;
  const float* srp = sr + base;
  float* dst = out + base;
  #pragma unroll
  for (int j=0;j<16;j++){
    float4 s = *(const float4*)&srp[4*j];
    float4 v;
    v.x = s.x + Osm[(size_t)(off+4*j+0)*132 + co];
    v.y = s.y + Osm[(size_t)(off+4*j+1)*132 + co];
    v.z = s.z + Osm[(size_t)(off+4*j+2)*132 + co];
    v.w = s.w + Osm[(size_t)(off+4*j+3)*132 + co];
    *(float4*)&dst[4*j] = v;
  }
}

// ---------------- launcher ----------------
extern "C" void kernel_launch(void* const* d_in, const int* in_sizes, int n_in,
                              void* d_out, int out_size){
  (void)in_sizes; (void)n_in; (void)out_size;
  const float* sr  =(const float*)d_in[0];
  const float* ctx =(const float*)d_in[1];
  const float* Wq  =(const float*)d_in[2];
  const float* bq  =(const float*)d_in[3];
  const float* Wk  =(const float*)d_in[4];
  const float* bk  =(const float*)d_in[5];
  const float* Wv  =(const float*)d_in[6];
  const float* bv  =(const float*)d_in[7];
  const float* Wp  =(const float*)d_in[8];
  const float* bp  =(const float*)d_in[9];
  const float* gm  =(const float*)d_in[10];
  float* out = (float*)d_out;

  const int SMEM_FLASH = 163840;            // 160KB
  const int SMEM_CONV3 = 67584 + 65536;     // 133120
  cudaFuncSetAttribute(flash_kernel, cudaFuncAttributeMaxDynamicSharedMemorySize, SMEM_FLASH);
  cudaFuncSetAttribute(conv3_kernel, cudaFuncAttributeMaxDynamicSharedMemorySize, SMEM_CONV3);

  conv1x1_kernel<CDIM,0><<<dim3(64,2,BATCH),256>>>(sr,  Wq, bq, NPIX);  // Q bf16 [n][c]
  conv1x1_kernel<CCTX,2><<<dim3(16,2,BATCH),256>>>(ctx, Wk, bk, NS);    // K fp32 [ms][c]
  conv1x1_kernel<CCTX,1><<<dim3(16,2,BATCH),256>>>(ctx, Wv, bv, NS);    // V fp32 [c][ms]
  upsample_last_kernel <<<dim3(HH,BATCH),256>>>();                      // -> g_kh bf16 [m][c]
  upsample_plane_kernel<<<dim3(CDIM,BATCH),256>>>();                    // -> g_vh bf16 [c][m]
  wt_kernel<<<576,256>>>(Wp);
  flash_kernel<<<dim3(32,BATCH),256,SMEM_FLASH>>>();
  conv3_kernel<<<dim3(HH/2,BATCH),256,SMEM_CONV3>>>(sr, bp, gm, out);
}

// round 17
// speedup vs baseline: 2.0092x; 1.0011x over previous
#include <cuda_runtime.h>
#include <cuda_bf16.h>
#include <cstdint>

#define BATCH 4
#define CDIM 128
#define CCTX 256
#define NPIX 4096
#define HS 32
#define NS 1024
#define HH 64
#define WW 64

// ---------------- scratch (device globals; no allocation) ----------------
__device__ __nv_bfloat16 g_qh[(size_t)BATCH*NPIX*CDIM];   // Q bf16 [b][n][c]
__device__ __nv_bfloat16 g_kh[(size_t)BATCH*NPIX*CDIM];   // K bf16 [b][m][c]
__device__ __nv_bfloat16 g_vh[(size_t)BATCH*CDIM*NPIX];   // V bf16 [b][c][m]
__device__ float g_kt[(size_t)BATCH*NS*CDIM];             // K conv out fp32 [b][ms][c]
__device__ float g_vs[(size_t)BATCH*CDIM*NS];             // V conv out fp32 [b][c][ms]
__device__ __nv_bfloat16 g_ah[(size_t)BATCH*NPIX*CDIM];   // attn out bf16 [b][n][c]
__device__ __nv_bfloat16 g_wh[9*CDIM*CDIM];               // Wp bf16 [tap][co][ci]

// ---------------- helpers ----------------
__device__ __forceinline__ uint32_t smem_u32(const void* p){
  uint32_t a;
  asm("{ .reg .u64 t; cvta.to.shared.u64 t, %1; cvt.u32.u64 %0, t; }" : "=r"(a) : "l"(p));
  return a;
}
__device__ __forceinline__ void cpasync16(void* sdst, const void* gsrc){
  uint32_t d = smem_u32(sdst);
  asm volatile("cp.async.cg.shared.global [%0], [%1], 16;" :: "r"(d), "l"(gsrc) : "memory");
}
#define CP_COMMIT() asm volatile("cp.async.commit_group;" ::: "memory")
#define CP_WAIT0()  asm volatile("cp.async.wait_group 0;" ::: "memory")
#define CP_WAIT1()  asm volatile("cp.async.wait_group 1;" ::: "memory")

// HMMA m16n8k16 bf16 -> fp32
__device__ __forceinline__ void mma16816(float* d, const uint32_t* a, const uint32_t* b){
  asm volatile("mma.sync.aligned.m16n8k16.row.col.f32.bf16.bf16.f32 "
    "{%0,%1,%2,%3}, {%4,%5,%6,%7}, {%8,%9}, {%0,%1,%2,%3};"
    : "+f"(d[0]), "+f"(d[1]), "+f"(d[2]), "+f"(d[3])
    : "r"(a[0]), "r"(a[1]), "r"(a[2]), "r"(a[3]), "r"(b[0]), "r"(b[1]));
}

// swizzled LDS of a bf16 pair: row-major rows of RW bf16 elems, w = pair index
template<int RW>
__device__ __forceinline__ uint32_t ldsw(const __nv_bfloat16* base, int r, int w){
  return *(const uint32_t*)(base + r*RW + 2*(w ^ ((r&7)<<2)));
}

// ---------------- 1x1 conv GEMM ----------------
// DST: 0 -> Q bf16 [b][n][c]; 1 -> g_vs fp32 [b][c][ms]; 2 -> g_kt fp32 [b][ms][c]
template<int CI, int DST>
__global__ __launch_bounds__(256) void conv1x1_kernel(
    const float* __restrict__ in, const float* __restrict__ W,
    const float* __restrict__ bias, int Npix)
{
  __shared__ float Ash[16][64];
  __shared__ float Bsh[16][68];
  const int n0 = blockIdx.x*64, co0 = blockIdx.y*64, b = blockIdx.z;
  const int tid = threadIdx.x, tx = tid & 15, ty = tid >> 4;
  const float* inb = in + (size_t)b*CI*Npix;
  float acc[4][4];
  #pragma unroll
  for (int i=0;i<4;i++)
    #pragma unroll
    for (int j=0;j<4;j++) acc[i][j]=0.f;

  for (int k0=0;k0<CI;k0+=16){
    __syncthreads();
    #pragma unroll
    for (int r=0;r<4;r++){
      int idx = tid + r*256;
      Ash[idx>>6][idx&63] = inb[(size_t)(k0+(idx>>6))*Npix + n0 + (idx&63)];
    }
    #pragma unroll
    for (int r=0;r<4;r++){
      int idx = tid + r*256;
      int cc = idx>>4, kk = idx&15;
      Bsh[kk][cc] = W[(size_t)(co0+cc)*CI + k0+kk];
    }
    __syncthreads();
    #pragma unroll
    for (int kk=0;kk<16;kk++){
      float a[4], bb[4];
      #pragma unroll
      for (int u=0;u<4;u++) a[u]=Ash[kk][tx*4+u];
      #pragma unroll
      for (int u=0;u<4;u++) bb[u]=Bsh[kk][ty*4+u];
      #pragma unroll
      for (int i=0;i<4;i++)
        #pragma unroll
        for (int j=0;j<4;j++) acc[i][j] += bb[i]*a[j];
    }
  }
  #pragma unroll
  for (int i=0;i<4;i++){
    int co = co0+ty*4+i;
    float bi = bias[co];
    #pragma unroll
    for (int j=0;j<4;j++){
      int n = n0+tx*4+j;
      float v = acc[i][j]+bi;
      if (DST==0)      g_qh[((size_t)b*NPIX + n)*CDIM + co] = __float2bfloat16(v);
      else if (DST==1) g_vs[((size_t)b*CDIM + co)*NS + n] = v;
      else             g_kt[((size_t)b*NS + n)*CDIM + co] = v;
    }
  }
}

// ---------------- bilinear 2x upsample helpers ----------------
__device__ __forceinline__ void bsrc(int o, int &i0, int &i1, float &w1){
  float s = 0.5f*(float)o - 0.25f;
  float f = floorf(s);
  w1 = s - f;
  int i = (int)f;
  i0 = i < 0 ? 0 : i;
  i1 = (i+1 > HS-1) ? (HS-1) : (i+1);
}

// V: [c][ms] fp32 -> [c][m] bf16
__global__ void upsample_plane_kernel(){
  __shared__ float sch[HS*HS];
  int c = blockIdx.x, b = blockIdx.y;
  const float* src = g_vs + ((size_t)b*CDIM + c)*NS;
  for (int i=threadIdx.x;i<NS;i+=256) sch[i]=src[i];
  __syncthreads();
  __nv_bfloat16* dst = g_vh + ((size_t)b*CDIM + c)*NPIX;
  for (int p=threadIdx.x;p<NPIX;p+=256){
    int h=p>>6, w=p&63;
    int y0,y1,x0,x1; float wy,wx;
    bsrc(h,y0,y1,wy); bsrc(w,x0,x1,wx);
    float v = (1.f-wy)*((1.f-wx)*sch[y0*HS+x0]+wx*sch[y0*HS+x1])
            +      wy *((1.f-wx)*sch[y1*HS+x0]+wx*sch[y1*HS+x1]);
    dst[p] = __float2bfloat16(v);
  }
}

// K: [ms][c] fp32 -> [m][c] bf16 (smem-cached rows, coalesced)
__global__ __launch_bounds__(256) void upsample_last_kernel(){
  __shared__ float rows[2][HS][CDIM];   // 32KB
  const int h = blockIdx.x, b = blockIdx.y, tid = threadIdx.x;
  int y0,y1; float wy; bsrc(h,y0,y1,wy);
  const float* src = g_kt + (size_t)b*NS*CDIM;
  const float4* s0 = (const float4*)(src + (size_t)y0*HS*CDIM);
  const float4* s1 = (const float4*)(src + (size_t)y1*HS*CDIM);
  float4* r0 = (float4*)&rows[0][0][0];
  float4* r1 = (float4*)&rows[1][0][0];
  #pragma unroll
  for (int i=0;i<4;i++){
    r0[tid + i*256] = s0[tid + i*256];
    r1[tid + i*256] = s1[tid + i*256];
  }
  __syncthreads();
  __nv_bfloat16* dst = g_kh + ((size_t)b*NPIX + (size_t)h*WW)*CDIM;
  const int c = tid & 127, w0 = tid >> 7;
  for (int w=w0; w<WW; w+=2){
    int x0,x1; float wx; bsrc(w,x0,x1,wx);
    float v = (1.f-wy)*((1.f-wx)*rows[0][x0][c] + wx*rows[0][x1][c])
            +      wy *((1.f-wx)*rows[1][x0][c] + wx*rows[1][x1][c]);
    dst[(size_t)w*CDIM + c] = __float2bfloat16(v);
  }
}

// ---------------- fused flash attention: O[n][c] = softmax_m(Q.K^T) . V^T --------------
// grid (32 n-tiles, B). block 256 = 8 warps; warp w owns n rows [w*16, w*16+16).
// smem: Qs 32KB | K bufs 2x32KB @32K,64K | V bufs 2x32KB @96K,128K  (160KB total)
// epilogue reuses @32K as 128x136 bf16 O staging -> g_ah [n][c].
__global__ __launch_bounds__(256,1) void flash_kernel(){
  extern __shared__ char smem[];
  __nv_bfloat16* Qs = (__nv_bfloat16*)smem;
  const int tid = threadIdx.x, lane = tid&31, wid = tid>>5;
  const int tig = lane&3, g = lane>>2;
  const int n0 = blockIdx.x*128, b = blockIdx.y;

  // Q tile resident
  const uint4* gq = (const uint4*)(g_qh + ((size_t)b*NPIX + n0)*CDIM);
  #pragma unroll
  for (int r=0;r<8;r++){
    int i = tid + r*256;
    int row = i>>4, seg = i&15;
    cpasync16(Qs + row*128 + ((seg ^ (row&7))<<3), gq + i);
  }
  CP_COMMIT();

  const uint4* gk = (const uint4*)(g_kh + (size_t)b*NPIX*CDIM);   // rows m, 16 uint4/row
  const uint4* gv = (const uint4*)(g_vh + (size_t)b*CDIM*NPIX);   // rows c, 512 uint4/row

  auto stage = [&](int mt, int buf){
    __nv_bfloat16* Kb = (__nv_bfloat16*)(smem + 32768 + buf*32768);
    __nv_bfloat16* Vb = (__nv_bfloat16*)(smem + 98304 + buf*32768);
    #pragma unroll
    for (int r=0;r<8;r++){
      int i = tid + r*256;
      int row = i>>4, seg = i&15;
      int so = row*128 + ((seg ^ (row&7))<<3);
      cpasync16(Kb + so, gk + (size_t)(mt*128 + row)*16 + seg);
      cpasync16(Vb + so, gv + (size_t)row*512 + mt*16 + seg);
    }
    CP_COMMIT();
  };

  float oacc[16][4];
  #pragma unroll
  for (int tj=0;tj<16;tj++)
    #pragma unroll
    for (int u=0;u<4;u++) oacc[tj][u]=0.f;
  float rs0 = 0.f, rs1 = 0.f;

  stage(0,0);
  stage(1,1);

  int buf = 0;
  const int rA = wid*16 + g;
  for (int mt=0; mt<32; mt++){
    if (mt==31) CP_WAIT0(); else CP_WAIT1();
    __syncthreads();
    const __nv_bfloat16* Kb = (const __nv_bfloat16*)(smem + 32768 + buf*32768);
    const __nv_bfloat16* Vb = (const __nv_bfloat16*)(smem + 98304 + buf*32768);

    // S = Q . K^T  (warp: 16n x 128m)
    float sacc[16][4];
    #pragma unroll
    for (int tj=0;tj<16;tj++)
      #pragma unroll
      for (int u=0;u<4;u++) sacc[tj][u]=0.f;
    #pragma unroll
    for (int ks=0;ks<8;ks++){
      const int w0 = ks*8 + tig;
      uint32_t aF[4];
      aF[0] = ldsw<128>(Qs, rA,   w0);
      aF[1] = ldsw<128>(Qs, rA+8, w0);
      aF[2] = ldsw<128>(Qs, rA,   w0+4);
      aF[3] = ldsw<128>(Qs, rA+8, w0+4);
      #pragma unroll
      for (int tj=0;tj<16;tj++){
        uint32_t bF[2];
        int rr = tj*8 + g;
        bF[0] = ldsw<128>(Kb, rr, w0);
        bF[1] = ldsw<128>(Kb, rr, w0+4);
        mma16816(sacc[tj], aF, bF);
      }
    }

    // P = exp(S): rowsum + pack acc->A fragments (FA2 identity)
    uint32_t aP[8][4];
    #pragma unroll
    for (int kk=0;kk<8;kk++){
      float e0=__expf(sacc[2*kk][0]),   e1=__expf(sacc[2*kk][1]);
      float e2=__expf(sacc[2*kk][2]),   e3=__expf(sacc[2*kk][3]);
      float f0=__expf(sacc[2*kk+1][0]), f1=__expf(sacc[2*kk+1][1]);
      float f2=__expf(sacc[2*kk+1][2]), f3=__expf(sacc[2*kk+1][3]);
      rs0 += e0+e1+f0+f1;
      rs1 += e2+e3+f2+f3;
      __nv_bfloat162 t;
      t=__floats2bfloat162_rn(e0,e1); aP[kk][0]=*(uint32_t*)&t;
      t=__floats2bfloat162_rn(e2,e3); aP[kk][1]=*(uint32_t*)&t;
      t=__floats2bfloat162_rn(f0,f1); aP[kk][2]=*(uint32_t*)&t;
      t=__floats2bfloat162_rn(f2,f3); aP[kk][3]=*(uint32_t*)&t;
    }

    // O += P . V^T  (warp: 16n x 128c, k = 128m from registers)
    #pragma unroll
    for (int kk=0;kk<8;kk++){
      const int w0 = kk*8 + tig;
      #pragma unroll
      for (int tj=0;tj<16;tj++){
        uint32_t bF[2];
        int rr = tj*8 + g;
        bF[0] = ldsw<128>(Vb, rr, w0);
        bF[1] = ldsw<128>(Vb, rr, w0+4);
        mma16816(oacc[tj], aP[kk], bF);
      }
    }

    __syncthreads();
    if (mt+2 < 32) stage(mt+2, buf);
    buf ^= 1;
  }

  // rowsum reduce across tig (cols)
  rs0 += __shfl_xor_sync(0xffffffffu, rs0, 1);
  rs0 += __shfl_xor_sync(0xffffffffu, rs0, 2);
  rs1 += __shfl_xor_sync(0xffffffffu, rs1, 1);
  rs1 += __shfl_xor_sync(0xffffffffu, rs1, 2);
  const float ri0 = 1.f/rs0, ri1 = 1.f/rs1;

  // stage O to smem as bf16 [128][136], then write g_ah [n][c] coalesced (256B rows)
  __syncthreads();
  __nv_bfloat16* Osm = (__nv_bfloat16*)(smem + 32768);
  #pragma unroll
  for (int tj=0;tj<16;tj++){
    int c = tj*8 + 2*tig;
    __nv_bfloat162 t0 = __floats2bfloat162_rn(oacc[tj][0]*ri0, oacc[tj][1]*ri0);
    __nv_bfloat162 t1 = __floats2bfloat162_rn(oacc[tj][2]*ri1, oacc[tj][3]*ri1);
    *(uint32_t*)&Osm[(size_t)rA*136 + c]     = *(uint32_t*)&t0;
    *(uint32_t*)&Osm[(size_t)(rA+8)*136 + c] = *(uint32_t*)&t1;
  }
  __syncthreads();
  const int row = tid>>1, off = (tid&1)*64;
  const uint4* srow = (const uint4*)&Osm[(size_t)row*136 + off];
  uint4* drow = (uint4*)(g_ah + ((size_t)b*NPIX + n0 + row)*CDIM + off);
  #pragma unroll
  for (int j=0;j<8;j++) drow[j] = srow[j];
}

// ---------------- Wp -> bf16 [tap][co][ci] ----------------
__global__ void wt_kernel(const float* __restrict__ Wp){
  int i = blockIdx.x*256+threadIdx.x;
  if (i < 9*CDIM*CDIM){
    int tap = i>>14, r = i&16383;
    int co = r>>7, ci = r&127;
    g_wh[i] = __float2bfloat16(Wp[((size_t)co*CDIM + ci)*9 + tap]);
  }
}

// ---------------- conv3x3 as per-tap HMMA implicit GEMM + residual ----------------
// grid (32 = HH/2 row-pairs, B). block 256 = 8 warps; warp tile 32px x 64co.
// smem: Att [4][66][128] bf16 (67584B, swizzled, zero halo) | W bufs 2x32KB @67584
// epilogue reuses Att region as [128][132] fp32 staging.
__global__ __launch_bounds__(256,1) void conv3_kernel(
  const float* __restrict__ sr, const float* __restrict__ bp,
  const float* __restrict__ gamma, float* __restrict__ out)
{
  extern __shared__ char smem[];
  __nv_bfloat16* Att = (__nv_bfloat16*)smem;
  const int tid = threadIdx.x, lane = tid&31, wid = tid>>5;
  const int tig = lane&3, g = lane>>2;
  const int wr = wid&3, wc = wid>>2;
  const int h0 = blockIdx.x*2, b = blockIdx.y;
  const uint4 z = make_uint4(0,0,0,0);

  // zero halo columns (w=0 and w=65 of each of 4 row-lines)
  if (tid < 128){
    int r = tid>>5, which = (tid>>4)&1, seg = tid&15;
    int rlin = r*66 + (which ? 65 : 0);
    *(uint4*)(Att + rlin*128 + ((seg ^ (rlin&7))<<3)) = z;
  }
  // att rows h0-1..h0+2 (cp.async valid rows, zero OOB rows)
  const __nv_bfloat16* gatt = g_ah + (size_t)b*NPIX*CDIM;
  #pragma unroll
  for (int r=0;r<4;r++){
    int hy = h0 - 1 + r;
    bool valid = (hy>=0 && hy<HH);
    #pragma unroll
    for (int it=0; it<4; it++){
      int i = tid + it*256;           // 0..1023
      int w = i>>4, seg = i&15;
      int rlin = r*66 + w + 1;
      void* dst = Att + rlin*128 + ((seg ^ (rlin&7))<<3);
      if (valid) cpasync16(dst, (const uint4*)(gatt + ((size_t)hy*WW + w)*CDIM) + seg);
      else      *(uint4*)dst = z;
    }
  }
  CP_COMMIT();

  auto wstage = [&](int tap, int bufw){
    __nv_bfloat16* Wb = (__nv_bfloat16*)(smem + 67584 + bufw*32768);
    const uint4* src = (const uint4*)(g_wh + (size_t)tap*CDIM*CDIM);
    #pragma unroll
    for (int rr=0;rr<8;rr++){
      int i = tid + rr*256;
      int row = i>>4, seg = i&15;
      cpasync16(Wb + row*128 + ((seg ^ (row&7))<<3), src + (size_t)row*16 + seg);
    }
    CP_COMMIT();
  };
  wstage(0,0);
  wstage(1,1);

  float acc[2][8][4];
  #pragma unroll
  for (int ti=0;ti<2;ti++)
    #pragma unroll
    for (int tj=0;tj<8;tj++)
      #pragma unroll
      for (int u=0;u<4;u++) acc[ti][tj][u]=0.f;

  int buf = 0;
  for (int tap=0; tap<9; tap++){
    if (tap==8) CP_WAIT0(); else CP_WAIT1();
    __syncthreads();
    const __nv_bfloat16* Wb = (const __nv_bfloat16*)(smem + 67584 + buf*32768);
    const int dy = tap/3 - 1, dx = tap%3 - 1;
    #pragma unroll
    for (int ks=0;ks<8;ks++){
      const int w0 = ks*8 + tig;
      uint32_t aF[2][4];
      #pragma unroll
      for (int ti=0;ti<2;ti++){
        int p = wr*32 + ti*16 + g;
        int rl  = ((p>>6)+1+dy)*66 + (p&63) + dx + 1;
        int rl2 = rl + 8;   // p+8 stays in same image row (16-aligned chunks)
        aF[ti][0] = ldsw<128>(Att, rl,  w0);
        aF[ti][1] = ldsw<128>(Att, rl2, w0);
        aF[ti][2] = ldsw<128>(Att, rl,  w0+4);
        aF[ti][3] = ldsw<128>(Att, rl2, w0+4);
      }
      #pragma unroll
      for (int tj=0;tj<8;tj++){
        int rr = wc*64 + tj*8 + g;
        uint32_t bF[2];
        bF[0] = ldsw<128>(Wb, rr, w0);
        bF[1] = ldsw<128>(Wb, rr, w0+4);
        #pragma unroll
        for (int ti=0;ti<2;ti++)
          mma16816(acc[ti][tj], aF[ti], bF);
      }
    }
    __syncthreads();
    if (tap+2 < 9) wstage(tap+2, buf);
    buf ^= 1;
  }

  // epilogue: gamma*(bp+acc) staged [128px][132] fp32, then out = sr + ... coalesced
  const float gm = gamma[0];
  float* Osm = (float*)smem;
  #pragma unroll
  for (int ti=0;ti<2;ti++){
    int p = wr*32 + ti*16 + g;
    #pragma unroll
    for (int tj=0;tj<8;tj++){
      int co = wc*64 + tj*8 + 2*tig;
      float b0 = __ldg(bp+co), b1 = __ldg(bp+co+1);
      Osm[(size_t)p*132 + co]       = gm*(b0 + acc[ti][tj][0]);
      Osm[(size_t)p*132 + co+1]     = gm*(b1 + acc[ti][tj][1]);
      Osm[(size_t)(p+8)*132 + co]   = gm*(b0 + acc[ti][tj][2]);
      Osm[(size_t)(p+8)*132 + co+1] = gm*(b1 + acc[ti][tj][3]);
    }
  }
  __syncthreads();
  const int co = tid>>1, off = (tid&1)*64;
  size_t base = ((size_t)b*CDIM + co)*NPIX + (size_t)h0*WW + off;
  const float* srp = sr + base;
  float* dst = out + base;
  #pragma unroll
  for (int j=0;j<16;j++){
    float4 s = *(const float4*)&srp[4*j];
    float4 v;
    v.x = s.x + Osm[(size_t)(off+4*j+0)*132 + co];
    v.y = s.y + Osm[(size_t)(off+4*j+1)*132 + co];
    v.z = s.z + Osm[(size_t)(off+4*j+2)*132 + co];
    v.w = s.w + Osm[(size_t)(off+4*j+3)*132 + co];
    *(float4*)&dst[4*j] = v;
  }
}

// ---------------- launcher ----------------
extern "C" void kernel_launch(void* const* d_in, const int* in_sizes, int n_in,
                              void* d_out, int out_size){
  (void)in_sizes; (void)n_in; (void)out_size;
  const float* sr  =(const float*)d_in[0];
  const float* ctx =(const float*)d_in[1];
  const float* Wq  =(const float*)d_in[2];
  const float* bq  =(const float*)d_in[3];
  const float* Wk  =(const float*)d_in[4];
  const float* bk  =(const float*)d_in[5];
  const float* Wv  =(const float*)d_in[6];
  const float* bv  =(const float*)d_in[7];
  const float* Wp  =(const float*)d_in[8];
  const float* bp  =(const float*)d_in[9];
  const float* gm  =(const float*)d_in[10];
  float* out = (float*)d_out;

  const int SMEM_FLASH = 163840;            // 160KB
  const int SMEM_CONV3 = 67584 + 65536;     // 133120
  cudaFuncSetAttribute(flash_kernel, cudaFuncAttributeMaxDynamicSharedMemorySize, SMEM_FLASH);
  cudaFuncSetAttribute(conv3_kernel, cudaFuncAttributeMaxDynamicSharedMemorySize, SMEM_CONV3);

  conv1x1_kernel<CDIM,0><<<dim3(64,2,BATCH),256>>>(sr,  Wq, bq, NPIX);  // Q bf16 [n][c]
  conv1x1_kernel<CCTX,2><<<dim3(16,2,BATCH),256>>>(ctx, Wk, bk, NS);    // K fp32 [ms][c]
  conv1x1_kernel<CCTX,1><<<dim3(16,2,BATCH),256>>>(ctx, Wv, bv, NS);    // V fp32 [c][ms]
  upsample_last_kernel <<<dim3(HH,BATCH),256>>>();                      // -> g_kh bf16 [m][c]
  upsample_plane_kernel<<<dim3(CDIM,BATCH),256>>>();                    // -> g_vh bf16 [c][m]
  wt_kernel<<<576,256>>>(Wp);
  flash_kernel<<<dim3(32,BATCH),256,SMEM_FLASH>>>();
  conv3_kernel<<<dim3(HH/2,BATCH),256,SMEM_CONV3>>>(sr, bp, gm, out);
}